// round 7
// baseline (speedup 1.0000x reference)
#include <cuda_runtime.h>
#include <math.h>
#include <stddef.h>

#define Hh 1024
#define FH 4096
#define Bb 64
#define Tt 512
#define Mm 32768   // B*T

typedef unsigned long long ull;

// Scratch (device globals: no runtime allocation).
__device__ float g_xp[(size_t)Mm * FH];     // gate preactivations, current layer
__device__ float g_hseq[(size_t)Mm * Hh];   // hidden sequence, current layer
__device__ float g_hA[Bb * Hh];
__device__ float g_hB[Bb * Hh];
__device__ unsigned g_bar;                  // grid-barrier counter

__device__ __forceinline__ void ffma2(ull &c, ull a, ull b) {
    asm("fma.rn.f32x2 %0, %1, %2, %0;" : "+l"(c) : "l"(a), "l"(b));
}
__device__ __forceinline__ float pairsum(ull v) {
    return __uint_as_float((unsigned)v) + __uint_as_float((unsigned)(v >> 32));
}

// ---------------------------------------------------------------------------
// xp[m][n] = sum_k A[m][k]*W[n][k] + bi[n] + bh[n];  M=32768, N=4096.
// 128x128 block tile, BK=8, 256 threads, 8x8 microtile. (unchanged from R4)
// ---------------------------------------------------------------------------
__global__ __launch_bounds__(256) void gemm_xp(
    const float* __restrict__ Ax, int useX, int K,
    const float* __restrict__ W,
    const float* __restrict__ bi, const float* __restrict__ bh)
{
    const float* A = useX ? Ax : g_hseq;
    __shared__ __align__(16) float As[8][128];
    __shared__ __align__(16) float Bs[8][128];
    const int tid = threadIdx.x;
    const int tx = tid & 15, ty = tid >> 4;
    const int n0 = blockIdx.x << 7, m0 = blockIdx.y << 7;
    const int ar = tid >> 1, ac = (tid & 1) * 4;
    const float* Ap = A + (size_t)(m0 + ar) * K + ac;
    const float* Wp = W + (size_t)(n0 + ar) * K + ac;

    float acc[8][8];
#pragma unroll
    for (int i = 0; i < 8; i++)
#pragma unroll
        for (int j = 0; j < 8; j++) acc[i][j] = 0.f;

    for (int kt = 0; kt < K; kt += 8) {
        float4 av = *(const float4*)(Ap + kt);
        float4 wv = *(const float4*)(Wp + kt);
        __syncthreads();
        As[ac + 0][ar] = av.x; As[ac + 1][ar] = av.y;
        As[ac + 2][ar] = av.z; As[ac + 3][ar] = av.w;
        Bs[ac + 0][ar] = wv.x; Bs[ac + 1][ar] = wv.y;
        Bs[ac + 2][ar] = wv.z; Bs[ac + 3][ar] = wv.w;
        __syncthreads();
#pragma unroll
        for (int k = 0; k < 8; k++) {
            float a[8], b[8];
            *(float4*)&a[0] = *(const float4*)&As[k][ty * 8];
            *(float4*)&a[4] = *(const float4*)&As[k][ty * 8 + 4];
            *(float4*)&b[0] = *(const float4*)&Bs[k][tx * 8];
            *(float4*)&b[4] = *(const float4*)&Bs[k][tx * 8 + 4];
#pragma unroll
            for (int i = 0; i < 8; i++)
#pragma unroll
                for (int j = 0; j < 8; j++) acc[i][j] += a[i] * b[j];
        }
    }
    float bias[8];
#pragma unroll
    for (int j = 0; j < 8; j++) {
        int n = n0 + tx * 8 + j;
        bias[j] = bi[n] + bh[n];
    }
#pragma unroll
    for (int i = 0; i < 8; i++) {
        float* op = g_xp + (size_t)(m0 + ty * 8 + i) * FH + n0 + tx * 8;
#pragma unroll
        for (int j = 0; j < 8; j++) op[j] = acc[i][j] + bias[j];
    }
}

__global__ void init_state()
{
    int i = blockIdx.x * blockDim.x + threadIdx.x;
    if (i == 0) g_bar = 0u;
    if (i < Bb * Hh) g_hA[i] = 0.f;
}

// ---------------------------------------------------------------------------
// Persistent recurrence: one launch runs all 512 timesteps for one layer.
// 128 blocks x 128 threads, 1 block/SM (all co-resident -> grid barrier safe).
// Block owns h-cols j0..j0+7 (32 gate rows). W slice (32x1024 = 128KB) lives
// in SMEM for the whole layer. Thread (rq=col, bq=batch-quad) owns ALL FOUR
// gates of (col j0+rq, batches 4bq..4bq+3): c stays in registers, no gate
// exchange. Inner product packed over k-pairs with fma.rn.f32x2.
// ---------------------------------------------------------------------------
#define WSTR 1028                       // W row stride (floats): conflict-free
#define HSTR 68                         // H tile row stride (floats)
#define SMEM_BYTES ((32 * WSTR + 2 * 64 * HSTR) * 4)

__global__ __launch_bounds__(128, 1) void lstm_persist(const float* __restrict__ Whh)
{
    extern __shared__ float smem[];
    float* Ws = smem;                   // [32][WSTR]
    float* Hsm = smem + 32 * WSTR;      // [2][64][HSTR]

    const int tid = threadIdx.x;
    const int j0 = blockIdx.x << 3;
    const int rq = tid & 7;             // column within block
    const int bq = tid >> 3;            // batch quad 0..15

    // Load W slice once: local row lw = gate*8 + col; global row = gate*1024+j0+col
    {
        const int lw = tid >> 2;                 // 0..31
        const int q4 = (tid & 3) * 256;          // k quarter
        const int grow = (lw >> 3) * Hh + j0 + (lw & 7);
        const float* wp = Whh + (size_t)grow * Hh + q4;
        float* wsp = Ws + lw * WSTR + q4;
#pragma unroll 8
        for (int c = 0; c < 64; c++)
            *(float4*)&wsp[c * 4] = *(const float4*)&wp[c * 4];
    }

    float c_reg[4] = {0.f, 0.f, 0.f, 0.f};

    // h tile-load map: 64 batches x 64 k per chunk, 8 float4 per thread
    const int hb = tid >> 1;
    const int hk = (tid & 1) * 32;

    for (int t = 0; t < Tt; t++) {
        const float* hp = (t & 1) ? g_hB : g_hA;
        float*       hn = (t & 1) ? g_hA : g_hB;

        // Prefetch xp for this step (independent of h -> hidden under GEMM)
        float xpv[4][4];
#pragma unroll
        for (int i = 0; i < 4; i++) {
            const float* xq = g_xp + ((size_t)(4 * bq + i) * Tt + t) * FH + j0 + rq;
#pragma unroll
            for (int j = 0; j < 4; j++) xpv[j][i] = xq[j * Hh];
        }

        ull acc[4][4];
#pragma unroll
        for (int j = 0; j < 4; j++)
#pragma unroll
            for (int i = 0; i < 4; i++) acc[j][i] = 0ull;

        // Prologue: prefetch h chunk 0 (ld.global.cg: L1 may be stale in-kernel)
        float4 pre[8];
        {
            const float* src = hp + (size_t)hb * Hh + hk;
#pragma unroll
            for (int q = 0; q < 8; q++) pre[q] = __ldcg((const float4*)(src + q * 4));
        }

        for (int kt = 0; kt < 16; kt++) {
            __syncthreads();
            float* hbuf = Hsm + (kt & 1) * (64 * HSTR);
            {
                float* dst = hbuf + hb * HSTR + hk;
#pragma unroll
                for (int q = 0; q < 8; q++) *(float4*)(dst + q * 4) = pre[q];
            }
            if (kt < 15) {
                const float* src = hp + (size_t)hb * Hh + (kt + 1) * 64 + hk;
#pragma unroll
                for (int q = 0; q < 8; q++) pre[q] = __ldcg((const float4*)(src + q * 4));
            }
            __syncthreads();
            const float* wk = Ws + kt * 64;
#pragma unroll
            for (int k4 = 0; k4 < 16; k4++) {
                ulonglong2 wv[4], hv[4];
#pragma unroll
                for (int j = 0; j < 4; j++)
                    wv[j] = *(const ulonglong2*)&wk[(j * 8 + rq) * WSTR + k4 * 4];
#pragma unroll
                for (int i = 0; i < 4; i++)
                    hv[i] = *(const ulonglong2*)&hbuf[(4 * bq + i) * HSTR + k4 * 4];
#pragma unroll
                for (int j = 0; j < 4; j++)
#pragma unroll
                    for (int i = 0; i < 4; i++) {
                        ffma2(acc[j][i], wv[j].x, hv[i].x);
                        ffma2(acc[j][i], wv[j].y, hv[i].y);
                    }
            }
        }

        // Elementwise LSTM update; c in registers.
#pragma unroll
        for (int i = 0; i < 4; i++) {
            const int b = 4 * bq + i;
            float gi = pairsum(acc[0][i]) + xpv[0][i];
            float gf = pairsum(acc[1][i]) + xpv[1][i];
            float gg = pairsum(acc[2][i]) + xpv[2][i];
            float go = pairsum(acc[3][i]) + xpv[3][i];
            float si = 1.f / (1.f + expf(-gi));
            float sf = 1.f / (1.f + expf(-gf));
            float so = 1.f / (1.f + expf(-go));
            float cn = sf * c_reg[i] + si * tanhf(gg);
            c_reg[i] = cn;
            float hv = so * tanhf(cn);
            hn[b * Hh + j0 + rq] = hv;
            g_hseq[((size_t)b * Tt + t) * Hh + j0 + rq] = hv;
        }

        // Grid barrier: monotonic counter, all 128 blocks resident.
        __threadfence();
        __syncthreads();
        if (tid == 0) {
            atomicAdd(&g_bar, 1u);
            const unsigned target = 128u * (unsigned)(t + 1);
            while (*(volatile unsigned*)&g_bar < target) { }
        }
        __syncthreads();
    }
}

__global__ void fc_kernel(const float* __restrict__ fw, const float* __restrict__ fb,
                          float* __restrict__ out)
{
    __shared__ float red[256];
    int b = blockIdx.x, tid = threadIdx.x;
    const float* h = g_hseq + ((size_t)b * Tt + (Tt - 1)) * Hh;
    float s = 0.f;
    for (int j = tid; j < Hh; j += 256) s += h[j] * fw[j];
    red[tid] = s;
    __syncthreads();
    for (int o = 128; o > 0; o >>= 1) {
        if (tid < o) red[tid] += red[tid + o];
        __syncthreads();
    }
    if (tid == 0) out[b] = red[0] + fb[0];
}

extern "C" void kernel_launch(void* const* d_in, const int* in_sizes, int n_in,
                              void* d_out, int out_size)
{
    const float* x      = (const float*)d_in[0];
    const float* Wih[3] = {(const float*)d_in[1], (const float*)d_in[2], (const float*)d_in[3]};
    const float* Whh    = (const float*)d_in[4];   // [3][4096][1024]
    const float* bih    = (const float*)d_in[5];   // [3][4096]
    const float* bhh    = (const float*)d_in[6];   // [3][4096]
    const float* fcw    = (const float*)d_in[7];   // [1][1024]
    const float* fcb    = (const float*)d_in[8];   // [1]
    float* out = (float*)d_out;

    cudaFuncSetAttribute(lstm_persist,
                         cudaFuncAttributeMaxDynamicSharedMemorySize, SMEM_BYTES);

    for (int l = 0; l < 3; l++) {
        int K = l ? Hh : 128;
        gemm_xp<<<dim3(32, 256), 256>>>(x, (l == 0) ? 1 : 0, K,
                                        Wih[l], bih + l * FH, bhh + l * FH);
        init_state<<<64, 1024>>>();
        lstm_persist<<<128, 128, SMEM_BYTES>>>(Whh + (size_t)l * FH * Hh);
    }
    fc_kernel<<<64, 256>>>(fcw, fcb, out);
}